// round 1
// baseline (speedup 1.0000x reference)
#include <cuda_runtime.h>
#include <cuda_bf16.h>

// Problem constants
#define BB    4
#define NN    2048
#define DX    384
#define DQH   48
#define HH    8
#define DVH   3072   // DX * HH

// Scratch (static device globals -- allocation-free per harness rules)
__device__ float g_Q[BB * DX  * NN];   // (b, h*48+q, n)
__device__ float g_K[BB * DX  * NN];   // (b, h*48+q, n)
__device__ float g_V[BB * DVH * NN];   // (b, h*384+v, n)
__device__ float g_R[BB * DVH * NN];   // (b, h*384+v, n)

// ---------------------------------------------------------------------------
// Projection GEMM: Out[b][m][n] = sum_d W[m][d] * X[b][n][d]
// Tiles: 64(m) x 64(n) x 32(d). 256 threads, 4x4 micro-tile.
// ---------------------------------------------------------------------------
__global__ __launch_bounds__(256)
void proj_kernel(const float* __restrict__ W, const float* __restrict__ X,
                 float* __restrict__ Out, int M)
{
    __shared__ float As[32][65];  // [d][m]
    __shared__ float Bs[32][65];  // [d][n]

    const int b  = blockIdx.z;
    const int n0 = blockIdx.x * 64;
    const int m0 = blockIdx.y * 64;
    const int tid = threadIdx.x;
    const int ty = tid >> 4;      // 0..15 -> m
    const int tx = tid & 15;      // 0..15 -> n

    const float* Xb = X + (size_t)b * NN * DX;

    float c[4][4];
#pragma unroll
    for (int i = 0; i < 4; i++)
#pragma unroll
        for (int j = 0; j < 4; j++) c[i][j] = 0.f;

    for (int kt = 0; kt < DX / 32; kt++) {
        const int k0 = kt * 32;
        // load W tile (64m x 32d) -> As[d][m]
#pragma unroll
        for (int it = 0; it < 8; it++) {
            int idx = tid + it * 256;
            int m = idx >> 5, d = idx & 31;
            As[d][m] = W[(size_t)(m0 + m) * DX + k0 + d];
        }
        // load X tile (64n x 32d) -> Bs[d][n]
#pragma unroll
        for (int it = 0; it < 8; it++) {
            int idx = tid + it * 256;
            int n = idx >> 5, d = idx & 31;
            Bs[d][n] = Xb[(size_t)(n0 + n) * DX + k0 + d];
        }
        __syncthreads();

#pragma unroll
        for (int kk = 0; kk < 32; kk++) {
            float a[4], bb[4];
#pragma unroll
            for (int i = 0; i < 4; i++) a[i]  = As[kk][ty * 4 + i];
#pragma unroll
            for (int j = 0; j < 4; j++) bb[j] = Bs[kk][tx * 4 + j];
#pragma unroll
            for (int i = 0; i < 4; i++)
#pragma unroll
                for (int j = 0; j < 4; j++) c[i][j] += a[i] * bb[j];
        }
        __syncthreads();
    }

    float* Ob = Out + (size_t)b * M * NN;
#pragma unroll
    for (int i = 0; i < 4; i++)
#pragma unroll
        for (int j = 0; j < 4; j++)
            Ob[(size_t)(m0 + ty * 4 + i) * NN + n0 + tx * 4 + j] = c[i][j];
}

// ---------------------------------------------------------------------------
// Flash attention: per (b, h, 32-query tile). Keys looped in tiles of 64.
// R[b][h*384+v][i] = sum_j V[v][j] * softmax_j(Q[:,i].K[:,j]/sqrt(48))
// ---------------------------------------------------------------------------
__global__ __launch_bounds__(256)
void attn_kernel(const float* __restrict__ Qg, const float* __restrict__ Kg,
                 const float* __restrict__ Vg, float* __restrict__ Rg)
{
    __shared__ float Qs[DQH][33];   // [q][i]   (Q pre-scaled by 1/sqrt(48))
    __shared__ float Ks[DQH][65];   // [q][j]
    __shared__ float Ss[32][68];    // [i][j]  scores then P (rows 16B-aligned)
    __shared__ float m_s[32], l_s[32], alpha_s[32];

    const int b  = blockIdx.z;
    const int h  = blockIdx.y;
    const int i0 = blockIdx.x * 32;
    const int tid = threadIdx.x;

    const float* Qp = Qg + (size_t)(b * DX + h * DQH) * NN;
    const float* Kp = Kg + (size_t)(b * DX + h * DQH) * NN;
    const float* Vp = Vg + (size_t)(b * DVH + h * DX) * NN;
    float*       Rp = Rg + (size_t)(b * DVH + h * DX) * NN;

    const float SCALE = 0.14433756729740643f; // 1/sqrt(48)

    // load + pre-scale Q tile: 48 x 32
#pragma unroll
    for (int it = 0; it < 6; it++) {
        int idx = tid + it * 256;
        int q = idx >> 5, i = idx & 31;
        Qs[q][i] = Qp[(size_t)q * NN + i0 + i] * SCALE;
    }
    if (tid < 32) { m_s[tid] = -1e30f; l_s[tid] = 0.f; }

    // accumulators: 12 v-rows x 4 query cols per thread
    const int ty = tid >> 3;       // 0..31 -> v group
    const int tx = tid & 7;        // 0..7  -> i group (4 queries)
    const int i_base = tx * 4;
    float acc[12][4];
#pragma unroll
    for (int vv = 0; vv < 12; vv++)
#pragma unroll
        for (int ii = 0; ii < 4; ii++) acc[vv][ii] = 0.f;

    const int sty = tid >> 4;      // 0..15 -> query pair for S
    const int stx = tid & 15;      // 0..15 -> 4 keys for S
    const int si = sty * 2, sj = stx * 4;

    const int r = tid >> 3;        // softmax row
    const int c = tid & 7;         // softmax 8-lane group

    for (int kt = 0; kt < NN / 64; kt++) {
        const int j0 = kt * 64;
        // load K tile 48 x 64
#pragma unroll
        for (int it = 0; it < 12; it++) {
            int idx = tid + it * 256;
            int q = idx >> 6, j = idx & 63;
            Ks[q][j] = Kp[(size_t)q * NN + j0 + j];
        }
        __syncthreads();

        // S = Q^T K (scaled): each thread 2x4
        float s00 = 0.f, s01 = 0.f, s02 = 0.f, s03 = 0.f;
        float s10 = 0.f, s11 = 0.f, s12 = 0.f, s13 = 0.f;
#pragma unroll
        for (int q = 0; q < DQH; q++) {
            float q0 = Qs[q][si], q1 = Qs[q][si + 1];
            float k0 = Ks[q][sj], k1 = Ks[q][sj + 1];
            float k2 = Ks[q][sj + 2], k3 = Ks[q][sj + 3];
            s00 += q0 * k0; s01 += q0 * k1; s02 += q0 * k2; s03 += q0 * k3;
            s10 += q1 * k0; s11 += q1 * k1; s12 += q1 * k2; s13 += q1 * k3;
        }
        Ss[si][sj] = s00; Ss[si][sj + 1] = s01; Ss[si][sj + 2] = s02; Ss[si][sj + 3] = s03;
        Ss[si + 1][sj] = s10; Ss[si + 1][sj + 1] = s11; Ss[si + 1][sj + 2] = s12; Ss[si + 1][sj + 3] = s13;
        __syncthreads();

        // online softmax: row r handled by 8 lanes (c), 8 elems each
        float mold = m_s[r];
        float pm = -1e30f;
#pragma unroll
        for (int k = 0; k < 8; k++) pm = fmaxf(pm, Ss[r][c * 8 + k]);
        pm = fmaxf(pm, __shfl_xor_sync(0xffffffffu, pm, 4));
        pm = fmaxf(pm, __shfl_xor_sync(0xffffffffu, pm, 2));
        pm = fmaxf(pm, __shfl_xor_sync(0xffffffffu, pm, 1));
        float mnew = fmaxf(mold, pm);
        float psum = 0.f;
#pragma unroll
        for (int k = 0; k < 8; k++) {
            float p = __expf(Ss[r][c * 8 + k] - mnew);
            Ss[r][c * 8 + k] = p;
            psum += p;
        }
        psum += __shfl_xor_sync(0xffffffffu, psum, 4);
        psum += __shfl_xor_sync(0xffffffffu, psum, 2);
        psum += __shfl_xor_sync(0xffffffffu, psum, 1);
        if (c == 0) {
            float al = __expf(mold - mnew);
            alpha_s[r] = al;
            l_s[r] = l_s[r] * al + psum;
            m_s[r] = mnew;
        }
        __syncthreads();

        // rescale accumulators then accumulate V @ P^T
        float a4[4];
#pragma unroll
        for (int ii = 0; ii < 4; ii++) a4[ii] = alpha_s[i_base + ii];
#pragma unroll
        for (int vv = 0; vv < 12; vv++)
#pragma unroll
            for (int ii = 0; ii < 4; ii++) acc[vv][ii] *= a4[ii];

        const float* Vt = Vp + j0;
        for (int j4 = 0; j4 < 16; j4++) {
            float4 pv[4];
#pragma unroll
            for (int ii = 0; ii < 4; ii++)
                pv[ii] = *(const float4*)&Ss[i_base + ii][j4 * 4];
#pragma unroll
            for (int vv = 0; vv < 12; vv++) {
                int v = ty * 12 + vv;
                float4 vf = *(const float4*)(Vt + (size_t)v * NN + j4 * 4);
#pragma unroll
                for (int ii = 0; ii < 4; ii++) {
                    acc[vv][ii] += vf.x * pv[ii].x;
                    acc[vv][ii] += vf.y * pv[ii].y;
                    acc[vv][ii] += vf.z * pv[ii].z;
                    acc[vv][ii] += vf.w * pv[ii].w;
                }
            }
        }
        // next iteration's K-load sync separates Ss reads from Ss rewrites
    }

    __syncthreads();
    float inv[4];
#pragma unroll
    for (int ii = 0; ii < 4; ii++) inv[ii] = 1.f / l_s[i_base + ii];
#pragma unroll
    for (int vv = 0; vv < 12; vv++) {
        int v = ty * 12 + vv;
#pragma unroll
        for (int ii = 0; ii < 4; ii++)
            Rp[(size_t)v * NN + i0 + i_base + ii] = acc[vv][ii] * inv[ii];
    }
}

// ---------------------------------------------------------------------------
// Output GEMM: out[b][n][d] = sum_v W_r[d][v] * R[b][v][n]
// Tiles: 64(n) x 64(d) x 32(v).
// ---------------------------------------------------------------------------
__global__ __launch_bounds__(256)
void outproj_kernel(const float* __restrict__ Wr, const float* __restrict__ Rg,
                    float* __restrict__ Out)
{
    __shared__ float As[32][65];  // [v][n]
    __shared__ float Bs[32][65];  // [v][d]

    const int b  = blockIdx.z;
    const int n0 = blockIdx.x * 64;
    const int d0 = blockIdx.y * 64;
    const int tid = threadIdx.x;
    const int ty = tid >> 4;      // -> n
    const int tx = tid & 15;      // -> d

    const float* Rb = Rg + (size_t)b * DVH * NN;

    float c[4][4];
#pragma unroll
    for (int i = 0; i < 4; i++)
#pragma unroll
        for (int j = 0; j < 4; j++) c[i][j] = 0.f;

    for (int kt = 0; kt < DVH / 32; kt++) {
        const int v0 = kt * 32;
        // R tile (32v x 64n) -> As[v][n]
#pragma unroll
        for (int it = 0; it < 8; it++) {
            int idx = tid + it * 256;
            int v = idx >> 6, n = idx & 63;
            As[v][n] = Rb[(size_t)(v0 + v) * NN + n0 + n];
        }
        // Wr tile (64d x 32v) -> Bs[v][d]
#pragma unroll
        for (int it = 0; it < 8; it++) {
            int idx = tid + it * 256;
            int d = idx >> 5, v = idx & 31;
            Bs[v][d] = Wr[(size_t)(d0 + d) * DVH + v0 + v];
        }
        __syncthreads();

#pragma unroll
        for (int kk = 0; kk < 32; kk++) {
            float a[4], bb[4];
#pragma unroll
            for (int i = 0; i < 4; i++) a[i]  = As[kk][ty * 4 + i];
#pragma unroll
            for (int j = 0; j < 4; j++) bb[j] = Bs[kk][tx * 4 + j];
#pragma unroll
            for (int i = 0; i < 4; i++)
#pragma unroll
                for (int j = 0; j < 4; j++) c[i][j] += a[i] * bb[j];
        }
        __syncthreads();
    }

    float* Ob = Out + (size_t)b * NN * DX;
#pragma unroll
    for (int i = 0; i < 4; i++)
#pragma unroll
        for (int j = 0; j < 4; j++)
            Ob[(size_t)(n0 + ty * 4 + i) * DX + d0 + tx * 4 + j] = c[i][j];
}

// ---------------------------------------------------------------------------
extern "C" void kernel_launch(void* const* d_in, const int* in_sizes, int n_in,
                              void* d_out, int out_size)
{
    const float* X   = (const float*)d_in[0];
    const float* W_q = (const float*)d_in[1];
    const float* W_k = (const float*)d_in[2];
    const float* W_v = (const float*)d_in[3];
    const float* W_r = (const float*)d_in[4];
    float* out = (float*)d_out;

    float *gQ, *gK, *gV, *gR;
    cudaGetSymbolAddress((void**)&gQ, g_Q);
    cudaGetSymbolAddress((void**)&gK, g_K);
    cudaGetSymbolAddress((void**)&gV, g_V);
    cudaGetSymbolAddress((void**)&gR, g_R);

    dim3 blk(256);
    // Q, K projections: M = 384
    proj_kernel<<<dim3(NN / 64, DX / 64, BB), blk>>>(W_q, X, gQ, DX);
    proj_kernel<<<dim3(NN / 64, DX / 64, BB), blk>>>(W_k, X, gK, DX);
    // V projection: M = 3072
    proj_kernel<<<dim3(NN / 64, DVH / 64, BB), blk>>>(W_v, X, gV, DVH);
    // fused attention
    attn_kernel<<<dim3(NN / 32, HH, BB), blk>>>(gQ, gK, gV, gR);
    // output projection
    outproj_kernel<<<dim3(NN / 64, DX / 64, BB), blk>>>(W_r, gR, out);
}

// round 2
// speedup vs baseline: 3.2994x; 3.2994x over previous
#include <cuda_runtime.h>
#include <cuda_bf16.h>

// Problem constants
#define BB    4
#define NN    2048
#define DX    384
#define DQH   48
#define HH    8
#define DVH   3072   // DX * HH

// Scratch (static device globals -- allocation-free per harness rules)
__device__ float g_Qt[(size_t)BB * NN * DX];    // [b][tok][qglob]   (n-major for S gemm)
__device__ float g_Kt[(size_t)BB * NN * DX];    // [b][tok][qglob]
__device__ float g_V [(size_t)BB * DVH * NN];   // [b][vglob][tok]   (m-major for R gemm)
__device__ float g_S [(size_t)BB * HH * NN * NN]; // [b][h][i][j]    scores -> P
__device__ float g_Rt[(size_t)BB * NN * DVH];   // [b][tok][vglob]   (n-major for out proj)

// ---------------------------------------------------------------------------
// tf32 helpers
// ---------------------------------------------------------------------------
__device__ __forceinline__ unsigned f2tf32(float x) {
    unsigned r;
    asm("cvt.rna.tf32.f32 %0, %1;" : "=r"(r) : "f"(x));
    return r;
}
__device__ __forceinline__ float4 cvt4(float4 v) {
    v.x = __uint_as_float(f2tf32(v.x));
    v.y = __uint_as_float(f2tf32(v.y));
    v.z = __uint_as_float(f2tf32(v.z));
    v.w = __uint_as_float(f2tf32(v.w));
    return v;
}

__device__ __forceinline__ void mma_tf32(float& d0, float& d1, float& d2, float& d3,
                                         unsigned a0, unsigned a1, unsigned a2, unsigned a3,
                                         unsigned b0, unsigned b1) {
    asm volatile(
        "mma.sync.aligned.m16n8k8.row.col.f32.tf32.tf32.f32 "
        "{%0,%1,%2,%3}, {%4,%5,%6,%7}, {%8,%9}, {%0,%1,%2,%3};\n"
        : "+f"(d0), "+f"(d1), "+f"(d2), "+f"(d3)
        : "r"(a0), "r"(a1), "r"(a2), "r"(a3), "r"(b0), "r"(b1));
}

// ---------------------------------------------------------------------------
// Generic tf32 GEMM:
//   D[m][n] = sum_k Asrc[m][k] * Bsrc[n][k]
// Asrc is m-major (row m, k contiguous, leading dim lda).
// Bsrc is n-major (row n, k contiguous, leading dim ldb).
// C address = Cbase + m*ldc_m + n*ldc_n.
// Two-level batching: batch index bi -> (b1 = bi/HB, b2 = bi%HB),
// pointer offsets b1*s?1 + b2*s?2.
// Block tile 128(M) x 64(N) x 16(K); 256 threads; warp tile 32x32.
// All dims must divide tiles exactly (they do for this problem).
// ---------------------------------------------------------------------------
__global__ __launch_bounds__(256)
void gemm_tf32(const float* __restrict__ A, const float* __restrict__ B,
               float* __restrict__ C,
               int K, int lda, int ldb,
               long sA1, long sA2, long sB1, long sB2, long sC1, long sC2,
               int ldc_m, int ldc_n, int HB)
{
    __shared__ float As[2][128][20];   // [buf][m][k] pad->20 (conflict-free frags)
    __shared__ float Bs[2][64][20];    // [buf][n][k]

    const int bi = blockIdx.z;
    const int b1 = bi / HB, b2 = bi - b1 * HB;
    const float* Ap = A + b1 * sA1 + b2 * sA2;
    const float* Bp = B + b1 * sB1 + b2 * sB2;
    float* Cp = C + b1 * sC1 + b2 * sC2;

    const int m0 = blockIdx.y * 128;
    const int n0 = blockIdx.x * 64;
    const int tid = threadIdx.x;
    const int lane = tid & 31;
    const int w = tid >> 5;
    const int wm = (w >> 1) * 32;   // warp m origin (0..96)
    const int wn = (w & 1) * 32;    // warp n origin (0 or 32)

    // staging load indices: A tile = 128x16 (512 float4, 2/thread), B = 64x16 (1/thread)
    const int arow = tid >> 2;          // 0..63 (second chunk +64)
    const int aquad = (tid & 3) * 4;
    const int brow = tid >> 2;
    const int bquad = (tid & 3) * 4;

    float acc[2][4][4];
#pragma unroll
    for (int mi = 0; mi < 2; mi++)
#pragma unroll
        for (int ni = 0; ni < 4; ni++)
#pragma unroll
            for (int r = 0; r < 4; r++) acc[mi][ni][r] = 0.f;

    const int ktiles = K / 16;

    // prologue: load k-tile 0
    float4 ra0 = *(const float4*)(Ap + (size_t)(m0 + arow) * lda + aquad);
    float4 ra1 = *(const float4*)(Ap + (size_t)(m0 + arow + 64) * lda + aquad);
    float4 rb  = *(const float4*)(Bp + (size_t)(n0 + brow) * ldb + bquad);
    *(float4*)&As[0][arow][aquad]      = cvt4(ra0);
    *(float4*)&As[0][arow + 64][aquad] = cvt4(ra1);
    *(float4*)&Bs[0][brow][bquad]      = cvt4(rb);
    __syncthreads();

    for (int kt = 0; kt < ktiles; kt++) {
        const int cur = kt & 1;
        const bool more = (kt + 1 < ktiles);
        float4 na0, na1, nb;
        if (more) {
            const int k0 = (kt + 1) * 16;
            na0 = *(const float4*)(Ap + (size_t)(m0 + arow) * lda + k0 + aquad);
            na1 = *(const float4*)(Ap + (size_t)(m0 + arow + 64) * lda + k0 + aquad);
            nb  = *(const float4*)(Bp + (size_t)(n0 + brow) * ldb + k0 + bquad);
        }

#pragma unroll
        for (int ks = 0; ks < 16; ks += 8) {
            unsigned afr[2][4];
            unsigned bfr[4][2];
            const int ar = wm + (lane >> 2);
            const int ac = ks + (lane & 3);
#pragma unroll
            for (int mi = 0; mi < 2; mi++) {
                afr[mi][0] = __float_as_uint(As[cur][ar + mi * 16][ac]);
                afr[mi][1] = __float_as_uint(As[cur][ar + mi * 16 + 8][ac]);
                afr[mi][2] = __float_as_uint(As[cur][ar + mi * 16][ac + 4]);
                afr[mi][3] = __float_as_uint(As[cur][ar + mi * 16 + 8][ac + 4]);
            }
#pragma unroll
            for (int ni = 0; ni < 4; ni++) {
                const int bn = wn + ni * 8 + (lane >> 2);
                bfr[ni][0] = __float_as_uint(Bs[cur][bn][ks + (lane & 3)]);
                bfr[ni][1] = __float_as_uint(Bs[cur][bn][ks + 4 + (lane & 3)]);
            }
#pragma unroll
            for (int mi = 0; mi < 2; mi++)
#pragma unroll
                for (int ni = 0; ni < 4; ni++)
                    mma_tf32(acc[mi][ni][0], acc[mi][ni][1], acc[mi][ni][2], acc[mi][ni][3],
                             afr[mi][0], afr[mi][1], afr[mi][2], afr[mi][3],
                             bfr[ni][0], bfr[ni][1]);
        }

        if (more) {
            const int nxt = cur ^ 1;
            *(float4*)&As[nxt][arow][aquad]      = cvt4(na0);
            *(float4*)&As[nxt][arow + 64][aquad] = cvt4(na1);
            *(float4*)&Bs[nxt][brow][bquad]      = cvt4(nb);
        }
        __syncthreads();
    }

    // epilogue: D[m][n] -> C[m*ldc_m + n*ldc_n]
#pragma unroll
    for (int mi = 0; mi < 2; mi++) {
        const int row = m0 + wm + mi * 16 + (lane >> 2);
#pragma unroll
        for (int ni = 0; ni < 4; ni++) {
            const int col = n0 + wn + ni * 8 + (lane & 3) * 2;
            Cp[(size_t)row * ldc_m + (size_t)col * ldc_n]           = acc[mi][ni][0];
            Cp[(size_t)row * ldc_m + (size_t)(col + 1) * ldc_n]     = acc[mi][ni][1];
            Cp[(size_t)(row + 8) * ldc_m + (size_t)col * ldc_n]     = acc[mi][ni][2];
            Cp[(size_t)(row + 8) * ldc_m + (size_t)(col + 1) * ldc_n] = acc[mi][ni][3];
        }
    }
}

// ---------------------------------------------------------------------------
// Row softmax over S (in place): one block per row of 2048.
// P[i][j] = exp(S*scale - max) / sum
// ---------------------------------------------------------------------------
__global__ __launch_bounds__(256)
void softmax_kernel(float* __restrict__ S)
{
    __shared__ float red[8];
    const float SC = 0.14433756729740643f;   // 1/sqrt(48)
    float* row = S + (size_t)blockIdx.x * NN;
    const int tid = threadIdx.x;
    const int lane = tid & 31;
    const int wp = tid >> 5;

    float4 v0 = ((const float4*)row)[tid];
    float4 v1 = ((const float4*)row)[tid + 256];
    v0.x *= SC; v0.y *= SC; v0.z *= SC; v0.w *= SC;
    v1.x *= SC; v1.y *= SC; v1.z *= SC; v1.w *= SC;

    float m = fmaxf(fmaxf(fmaxf(v0.x, v0.y), fmaxf(v0.z, v0.w)),
                    fmaxf(fmaxf(v1.x, v1.y), fmaxf(v1.z, v1.w)));
#pragma unroll
    for (int off = 16; off > 0; off >>= 1)
        m = fmaxf(m, __shfl_xor_sync(0xffffffffu, m, off));
    if (lane == 0) red[wp] = m;
    __syncthreads();
    float M = red[0];
#pragma unroll
    for (int i = 1; i < 8; i++) M = fmaxf(M, red[i]);
    __syncthreads();

    v0.x = __expf(v0.x - M); v0.y = __expf(v0.y - M);
    v0.z = __expf(v0.z - M); v0.w = __expf(v0.w - M);
    v1.x = __expf(v1.x - M); v1.y = __expf(v1.y - M);
    v1.z = __expf(v1.z - M); v1.w = __expf(v1.w - M);

    float s = v0.x + v0.y + v0.z + v0.w + v1.x + v1.y + v1.z + v1.w;
#pragma unroll
    for (int off = 16; off > 0; off >>= 1)
        s += __shfl_xor_sync(0xffffffffu, s, off);
    if (lane == 0) red[wp] = s;
    __syncthreads();
    float tot = red[0] + red[1] + red[2] + red[3] + red[4] + red[5] + red[6] + red[7];
    float inv = 1.f / tot;

    v0.x *= inv; v0.y *= inv; v0.z *= inv; v0.w *= inv;
    v1.x *= inv; v1.y *= inv; v1.z *= inv; v1.w *= inv;
    ((float4*)row)[tid] = v0;
    ((float4*)row)[tid + 256] = v1;
}

// ---------------------------------------------------------------------------
extern "C" void kernel_launch(void* const* d_in, const int* in_sizes, int n_in,
                              void* d_out, int out_size)
{
    const float* X   = (const float*)d_in[0];
    const float* W_q = (const float*)d_in[1];
    const float* W_k = (const float*)d_in[2];
    const float* W_v = (const float*)d_in[3];
    const float* W_r = (const float*)d_in[4];
    float* out = (float*)d_out;

    float *gQt, *gKt, *gV, *gS, *gRt;
    cudaGetSymbolAddress((void**)&gQt, g_Qt);
    cudaGetSymbolAddress((void**)&gKt, g_Kt);
    cudaGetSymbolAddress((void**)&gV,  g_V);
    cudaGetSymbolAddress((void**)&gS,  g_S);
    cudaGetSymbolAddress((void**)&gRt, g_Rt);

    const dim3 blk(256);

    // Q projection: D[q][tok] = sum_d W_q[q][d] X[tok][d]; store g_Qt[b][tok][q]
    gemm_tf32<<<dim3(NN / 64, DX / 128, BB), blk>>>(
        W_q, X, gQt, DX, DX, DX,
        0, 0, (long)NN * DX, 0, (long)NN * DX, 0,
        1, DX, 1);

    // K projection -> g_Kt[b][tok][q]
    gemm_tf32<<<dim3(NN / 64, DX / 128, BB), blk>>>(
        W_k, X, gKt, DX, DX, DX,
        0, 0, (long)NN * DX, 0, (long)NN * DX, 0,
        1, DX, 1);

    // V projection: D[v][tok] -> g_V[b][v][tok]
    gemm_tf32<<<dim3(NN / 64, DVH / 128, BB), blk>>>(
        W_v, X, gV, DX, DX, DX,
        0, 0, (long)NN * DX, 0, (long)DVH * NN, 0,
        NN, 1, 1);

    // Scores: S[i][j] = sum_q Qt[i][q] Kt[j][q]  per (b,h); store g_S[b][h][i][j]
    gemm_tf32<<<dim3(NN / 64, NN / 128, BB * HH), blk>>>(
        gQt, gKt, gS, DQH, DX, DX,
        (long)NN * DX, DQH,
        (long)NN * DX, DQH,
        (long)HH * NN * NN, (long)NN * NN,
        NN, 1, HH);

    // Softmax rows (applies 1/sqrt(48) scale)
    softmax_kernel<<<BB * HH * NN, blk>>>(gS);

    // R = V @ P^T: D[v][i] = sum_j V[v][j] P[i][j]; store g_Rt[b][i][h*384+v]
    gemm_tf32<<<dim3(NN / 64, DX / 128, BB * HH), blk>>>(
        gV, gS, gRt, NN, NN, NN,
        (long)DVH * NN, (long)DX * NN,
        (long)HH * NN * NN, (long)NN * NN,
        (long)NN * DVH, DX,
        1, DVH, HH);

    // Output projection: D[d][tok] = sum_v W_r[d][v] Rt[tok][v]; store out[b][tok][d]
    gemm_tf32<<<dim3(NN / 64, DX / 128, BB), blk>>>(
        W_r, gRt, out, DVH, DVH, DVH,
        0, 0, (long)NN * DVH, 0, (long)NN * DX, 0,
        1, DX, 1);
}

// round 3
// speedup vs baseline: 4.6423x; 1.4070x over previous
#include <cuda_runtime.h>
#include <cuda_bf16.h>

// Problem constants
#define BB    4
#define NN    2048
#define DX    384
#define DQH   48
#define HH    8
#define DVH   3072   // DX * HH

// Scratch
__device__ float g_Qt[(size_t)BB * NN * DX];    // [b][tok][qglob]  (tf32-rounded)
__device__ float g_Kt[(size_t)BB * NN * DX];    // [b][tok][qglob]  (tf32-rounded)
__device__ float g_V [(size_t)BB * DVH * NN];   // [b][vglob][tok]  (tf32-rounded)
__device__ float g_Rt[(size_t)BB * NN * DVH];   // [b][tok][vglob]

// ---------------------------------------------------------------------------
// helpers
// ---------------------------------------------------------------------------
__device__ __forceinline__ unsigned f2tf32(float x) {
    unsigned r;
    asm("cvt.rna.tf32.f32 %0, %1;" : "=r"(r) : "f"(x));
    return r;
}
__device__ __forceinline__ float4 cvt4(float4 v) {
    v.x = __uint_as_float(f2tf32(v.x));
    v.y = __uint_as_float(f2tf32(v.y));
    v.z = __uint_as_float(f2tf32(v.z));
    v.w = __uint_as_float(f2tf32(v.w));
    return v;
}
__device__ __forceinline__ void mma_tf32(float& d0, float& d1, float& d2, float& d3,
                                         unsigned a0, unsigned a1, unsigned a2, unsigned a3,
                                         unsigned b0, unsigned b1) {
    asm volatile(
        "mma.sync.aligned.m16n8k8.row.col.f32.tf32.tf32.f32 "
        "{%0,%1,%2,%3}, {%4,%5,%6,%7}, {%8,%9}, {%0,%1,%2,%3};\n"
        : "+f"(d0), "+f"(d1), "+f"(d2), "+f"(d3)
        : "r"(a0), "r"(a1), "r"(a2), "r"(a3), "r"(b0), "r"(b1));
}
__device__ __forceinline__ void ldsm4(unsigned& r0, unsigned& r1, unsigned& r2, unsigned& r3,
                                      unsigned addr) {
    asm volatile("ldmatrix.sync.aligned.m8n8.x4.shared.b16 {%0,%1,%2,%3}, [%4];\n"
                 : "=r"(r0), "=r"(r1), "=r"(r2), "=r"(r3) : "r"(addr));
}
__device__ __forceinline__ void cpa16(unsigned s, const void* g) {
    asm volatile("cp.async.cg.shared.global [%0], [%1], 16;\n" :: "r"(s), "l"(g));
}
#define CP_COMMIT() asm volatile("cp.async.commit_group;\n" ::)
#define CP_WAIT(n)  asm volatile("cp.async.wait_group " #n ";\n" ::)

// ---------------------------------------------------------------------------
// Generic tf32 GEMM (as round 2) + optional tf32 rounding of outputs.
// D[m][n] = sum_k A[m][k] * B[n][k];  C addr = m*ldc_m + n*ldc_n.
// ---------------------------------------------------------------------------
__global__ __launch_bounds__(256)
void gemm_tf32(const float* __restrict__ A, const float* __restrict__ B,
               float* __restrict__ C,
               int K, int lda, int ldb,
               long sA1, long sA2, long sB1, long sB2, long sC1, long sC2,
               int ldc_m, int ldc_n, int HB, int cvt)
{
    __shared__ float As[2][128][20];
    __shared__ float Bs[2][64][20];

    const int bi = blockIdx.z;
    const int b1 = bi / HB, b2 = bi - b1 * HB;
    const float* Ap = A + b1 * sA1 + b2 * sA2;
    const float* Bp = B + b1 * sB1 + b2 * sB2;
    float* Cp = C + b1 * sC1 + b2 * sC2;

    const int m0 = blockIdx.y * 128;
    const int n0 = blockIdx.x * 64;
    const int tid = threadIdx.x;
    const int lane = tid & 31;
    const int w = tid >> 5;
    const int wm = (w >> 1) * 32;
    const int wn = (w & 1) * 32;

    const int arow = tid >> 2;
    const int aquad = (tid & 3) * 4;

    float acc[2][4][4];
#pragma unroll
    for (int mi = 0; mi < 2; mi++)
#pragma unroll
        for (int ni = 0; ni < 4; ni++)
#pragma unroll
            for (int r = 0; r < 4; r++) acc[mi][ni][r] = 0.f;

    const int ktiles = K / 16;

    float4 ra0 = *(const float4*)(Ap + (size_t)(m0 + arow) * lda + aquad);
    float4 ra1 = *(const float4*)(Ap + (size_t)(m0 + arow + 64) * lda + aquad);
    float4 rb  = *(const float4*)(Bp + (size_t)(n0 + arow) * ldb + aquad);
    *(float4*)&As[0][arow][aquad]      = cvt4(ra0);
    *(float4*)&As[0][arow + 64][aquad] = cvt4(ra1);
    *(float4*)&Bs[0][arow][aquad]      = cvt4(rb);
    __syncthreads();

    for (int kt = 0; kt < ktiles; kt++) {
        const int cur = kt & 1;
        const bool more = (kt + 1 < ktiles);
        float4 na0, na1, nb;
        if (more) {
            const int k0 = (kt + 1) * 16;
            na0 = *(const float4*)(Ap + (size_t)(m0 + arow) * lda + k0 + aquad);
            na1 = *(const float4*)(Ap + (size_t)(m0 + arow + 64) * lda + k0 + aquad);
            nb  = *(const float4*)(Bp + (size_t)(n0 + arow) * ldb + k0 + aquad);
        }

#pragma unroll
        for (int ks = 0; ks < 16; ks += 8) {
            unsigned afr[2][4], bfr[4][2];
            const int ar = wm + (lane >> 2);
            const int ac = ks + (lane & 3);
#pragma unroll
            for (int mi = 0; mi < 2; mi++) {
                afr[mi][0] = __float_as_uint(As[cur][ar + mi * 16][ac]);
                afr[mi][1] = __float_as_uint(As[cur][ar + mi * 16 + 8][ac]);
                afr[mi][2] = __float_as_uint(As[cur][ar + mi * 16][ac + 4]);
                afr[mi][3] = __float_as_uint(As[cur][ar + mi * 16 + 8][ac + 4]);
            }
#pragma unroll
            for (int ni = 0; ni < 4; ni++) {
                const int bn = wn + ni * 8 + (lane >> 2);
                bfr[ni][0] = __float_as_uint(Bs[cur][bn][ks + (lane & 3)]);
                bfr[ni][1] = __float_as_uint(Bs[cur][bn][ks + 4 + (lane & 3)]);
            }
#pragma unroll
            for (int mi = 0; mi < 2; mi++)
#pragma unroll
                for (int ni = 0; ni < 4; ni++)
                    mma_tf32(acc[mi][ni][0], acc[mi][ni][1], acc[mi][ni][2], acc[mi][ni][3],
                             afr[mi][0], afr[mi][1], afr[mi][2], afr[mi][3],
                             bfr[ni][0], bfr[ni][1]);
        }

        if (more) {
            const int nxt = cur ^ 1;
            *(float4*)&As[nxt][arow][aquad]      = cvt4(na0);
            *(float4*)&As[nxt][arow + 64][aquad] = cvt4(na1);
            *(float4*)&Bs[nxt][arow][aquad]      = cvt4(nb);
        }
        __syncthreads();
    }

#pragma unroll
    for (int mi = 0; mi < 2; mi++) {
        const int row = m0 + wm + mi * 16 + (lane >> 2);
#pragma unroll
        for (int ni = 0; ni < 4; ni++) {
            const int col = n0 + wn + ni * 8 + (lane & 3) * 2;
            float v0 = acc[mi][ni][0], v1 = acc[mi][ni][1];
            float v2 = acc[mi][ni][2], v3 = acc[mi][ni][3];
            if (cvt) {
                v0 = __uint_as_float(f2tf32(v0)); v1 = __uint_as_float(f2tf32(v1));
                v2 = __uint_as_float(f2tf32(v2)); v3 = __uint_as_float(f2tf32(v3));
            }
            Cp[(size_t)row * ldc_m + (size_t)col * ldc_n]             = v0;
            Cp[(size_t)row * ldc_m + (size_t)(col + 1) * ldc_n]       = v1;
            Cp[(size_t)(row + 8) * ldc_m + (size_t)col * ldc_n]       = v2;
            Cp[(size_t)(row + 8) * ldc_m + (size_t)(col + 1) * ldc_n] = v3;
        }
    }
}

// ---------------------------------------------------------------------------
// Fused flash attention, tf32 tensor cores.
// Block: (b, h, 128-query tile), 512 threads (16 warps). Key tiles of 64.
// smem (floats): Qs[128][52] | Ks[2][64][52] | Ps[128][68] | Vst[384][68]
//                | m[128] | l[128] | alpha[128]
// ---------------------------------------------------------------------------
#define QS_OFF   0
#define KS_OFF   6656           // 128*52
#define KS_SZ    3328           // 64*52
#define PS_OFF   13312          // KS_OFF + 2*KS_SZ
#define VS_OFF   22016          // PS_OFF + 128*68
#define MS_OFF   48128          // VS_OFF + 384*68
#define LS_OFF   48256
#define AL_OFF   48384
#define SM_FLOATS 48512         // total = 194048 bytes

__global__ __launch_bounds__(512)
void attn_fused(const float* __restrict__ Qt, const float* __restrict__ Kt,
                const float* __restrict__ Vg, float* __restrict__ Rt)
{
    extern __shared__ float sm[];
    const unsigned smb = (unsigned)__cvta_generic_to_shared(sm);

    const int b  = blockIdx.z;
    const int h  = blockIdx.y;
    const int i0 = blockIdx.x * 128;
    const int tid = threadIdx.x;
    const int lane = tid & 31;
    const int w = tid >> 5;

    const float* Qp = Qt + (size_t)b * NN * DX + (size_t)i0 * DX + h * DQH;
    const float* Kp = Kt + (size_t)b * NN * DX + h * DQH;
    const float* Vp = Vg + ((size_t)b * DVH + h * DX) * NN;

    // warp tiling: S phase 4x4 (32m x 16n); PV phase 4x4 (32m x 96n)
    const int wm  = (w >> 2) * 32;
    const int wnS = (w & 3) * 16;
    const int wn  = (w & 3) * 96;

    // ---- stage Q (once) + K tile 0, V tile 0 ----
#pragma unroll
    for (int r = 0; r < 3; r++) {
        int idx = tid + r * 512;                 // < 1536
        int row = idx / 12, q = idx % 12;
        cpa16(smb + (QS_OFF + row * 52 + q * 4) * 4, Qp + (size_t)row * DX + q * 4);
    }
    {   // K tile 0 -> buf 0
        int idx = tid;
        int row = idx / 12, q = idx % 12;
        cpa16(smb + (KS_OFF + row * 52 + q * 4) * 4, Kp + (size_t)row * DX + q * 4);
        idx = tid + 512;
        if (idx < 768) {
            row = idx / 12; q = idx % 12;
            cpa16(smb + (KS_OFF + row * 52 + q * 4) * 4, Kp + (size_t)row * DX + q * 4);
        }
    }
    CP_COMMIT();   // group: Q + K0
#pragma unroll
    for (int r = 0; r < 12; r++) {
        int idx = tid + r * 512;                 // < 6144
        int v = idx / 16, q = idx % 16;
        cpa16(smb + (VS_OFF + v * 68 + q * 4) * 4, Vp + (size_t)v * NN + q * 4);
    }
    CP_COMMIT();   // group: V0

    if (tid < 128) { sm[MS_OFF + tid] = -1e30f; sm[LS_OFF + tid] = 0.f; }

    float acc[2][12][4];
#pragma unroll
    for (int mi = 0; mi < 2; mi++)
#pragma unroll
        for (int ni = 0; ni < 12; ni++)
#pragma unroll
            for (int r = 0; r < 4; r++) acc[mi][ni][r] = 0.f;

    const float SC = 0.14433756729740643f;   // 1/sqrt(48)

    for (int t = 0; t < NN / 64; t++) {
        const int cur = t & 1;
        // prefetch K(t+1)
        if (t + 1 < NN / 64) {
            const float* Kn = Kp + (size_t)(t + 1) * 64 * DX;
            int idx = tid;
            int row = idx / 12, q = idx % 12;
            cpa16(smb + (KS_OFF + (cur ^ 1) * KS_SZ + row * 52 + q * 4) * 4,
                  Kn + (size_t)row * DX + q * 4);
            idx = tid + 512;
            if (idx < 768) {
                row = idx / 12; q = idx % 12;
                cpa16(smb + (KS_OFF + (cur ^ 1) * KS_SZ + row * 52 + q * 4) * 4,
                      Kn + (size_t)row * DX + q * 4);
            }
        }
        CP_COMMIT();
        CP_WAIT(2);          // K(t) (and Q) resident
        __syncthreads();     // also: everyone done with prev PV (Ps reusable)

        // ---- S = Q K^T  (m 32 x n 16 per warp) ----
        {
            float sacc[2][2][4];
#pragma unroll
            for (int mi = 0; mi < 2; mi++)
#pragma unroll
                for (int ni = 0; ni < 2; ni++)
#pragma unroll
                    for (int r = 0; r < 4; r++) sacc[mi][ni][r] = 0.f;

#pragma unroll
            for (int ks = 0; ks < 6; ks++) {
                unsigned q0, q1, q2, q3;
                {   // B frags from Ks: covers ni 0,1
                    int row = wnS + ((lane >> 4) & 1) * 8 + (lane & 7);
                    int col = ks * 8 + ((lane >> 3) & 1) * 4;
                    ldsm4(q0, q1, q2, q3,
                          smb + (KS_OFF + cur * KS_SZ + row * 52 + col) * 4);
                }
#pragma unroll
                for (int mi = 0; mi < 2; mi++) {
                    unsigned a0, a1, a2, a3;
                    int row = wm + mi * 16 + (lane & 15);
                    int col = ks * 8 + (lane >> 4) * 4;
                    ldsm4(a0, a1, a2, a3, smb + (QS_OFF + row * 52 + col) * 4);
                    mma_tf32(sacc[mi][0][0], sacc[mi][0][1], sacc[mi][0][2], sacc[mi][0][3],
                             a0, a1, a2, a3, q0, q1);
                    mma_tf32(sacc[mi][1][0], sacc[mi][1][1], sacc[mi][1][2], sacc[mi][1][3],
                             a0, a1, a2, a3, q2, q3);
                }
            }
            // store S to Ps
#pragma unroll
            for (int mi = 0; mi < 2; mi++) {
                int r0 = wm + mi * 16 + (lane >> 2);
#pragma unroll
                for (int ni = 0; ni < 2; ni++) {
                    int c0 = wnS + ni * 8 + (lane & 3) * 2;
                    *(float2*)&sm[PS_OFF + r0 * 68 + c0] =
                        make_float2(sacc[mi][ni][0], sacc[mi][ni][1]);
                    *(float2*)&sm[PS_OFF + (r0 + 8) * 68 + c0] =
                        make_float2(sacc[mi][ni][2], sacc[mi][ni][3]);
                }
            }
        }
        __syncthreads();

        // ---- online softmax on Ps rows (512 thr: 4 per row, 16 cols each) ----
        {
            const int r = tid >> 2;
            const int c = tid & 3;
            float* row = &sm[PS_OFF + r * 68 + c * 16];
            float4 x0 = *(float4*)(row + 0);
            float4 x1 = *(float4*)(row + 4);
            float4 x2 = *(float4*)(row + 8);
            float4 x3 = *(float4*)(row + 12);
            float pm = fmaxf(fmaxf(fmaxf(x0.x, x0.y), fmaxf(x0.z, x0.w)),
                             fmaxf(fmaxf(x1.x, x1.y), fmaxf(x1.z, x1.w)));
            pm = fmaxf(pm, fmaxf(fmaxf(fmaxf(x2.x, x2.y), fmaxf(x2.z, x2.w)),
                                 fmaxf(fmaxf(x3.x, x3.y), fmaxf(x3.z, x3.w))));
            pm = fmaxf(pm, __shfl_xor_sync(0xffffffffu, pm, 1));
            pm = fmaxf(pm, __shfl_xor_sync(0xffffffffu, pm, 2));
            float mold = sm[MS_OFF + r];
            float mnew = fmaxf(mold, pm);
#define EXP1(v) v = __uint_as_float(f2tf32(__expf((v - mnew) * SC)))
            EXP1(x0.x); EXP1(x0.y); EXP1(x0.z); EXP1(x0.w);
            EXP1(x1.x); EXP1(x1.y); EXP1(x1.z); EXP1(x1.w);
            EXP1(x2.x); EXP1(x2.y); EXP1(x2.z); EXP1(x2.w);
            EXP1(x3.x); EXP1(x3.y); EXP1(x3.z); EXP1(x3.w);
#undef EXP1
            float ps = x0.x + x0.y + x0.z + x0.w + x1.x + x1.y + x1.z + x1.w
                     + x2.x + x2.y + x2.z + x2.w + x3.x + x3.y + x3.z + x3.w;
            ps += __shfl_xor_sync(0xffffffffu, ps, 1);
            ps += __shfl_xor_sync(0xffffffffu, ps, 2);
            *(float4*)(row + 0)  = x0;
            *(float4*)(row + 4)  = x1;
            *(float4*)(row + 8)  = x2;
            *(float4*)(row + 12) = x3;
            if (c == 0) {
                float al = __expf((mold - mnew) * SC);
                sm[AL_OFF + r] = al;
                sm[LS_OFF + r] = sm[LS_OFF + r] * al + ps;
                sm[MS_OFF + r] = mnew;
            }
        }
        __syncthreads();
        CP_WAIT(1);          // V(t) resident
        __syncthreads();

        // ---- PV: O += P V  (m 32 x n 96 per warp) ----
        {
            float al[2][2];
#pragma unroll
            for (int mi = 0; mi < 2; mi++) {
                al[mi][0] = sm[AL_OFF + wm + mi * 16 + (lane >> 2)];
                al[mi][1] = sm[AL_OFF + wm + mi * 16 + 8 + (lane >> 2)];
            }
#pragma unroll
            for (int mi = 0; mi < 2; mi++)
#pragma unroll
                for (int ni = 0; ni < 12; ni++) {
                    acc[mi][ni][0] *= al[mi][0]; acc[mi][ni][1] *= al[mi][0];
                    acc[mi][ni][2] *= al[mi][1]; acc[mi][ni][3] *= al[mi][1];
                }

#pragma unroll
            for (int ks = 0; ks < 8; ks++) {
                unsigned afr[2][4];
#pragma unroll
                for (int mi = 0; mi < 2; mi++) {
                    int row = wm + mi * 16 + (lane & 15);
                    int col = ks * 8 + (lane >> 4) * 4;
                    ldsm4(afr[mi][0], afr[mi][1], afr[mi][2], afr[mi][3],
                          smb + (PS_OFF + row * 68 + col) * 4);
                }
#pragma unroll
                for (int nip = 0; nip < 6; nip++) {
                    unsigned q0, q1, q2, q3;
                    int row = wn + nip * 16 + ((lane >> 4) & 1) * 8 + (lane & 7);
                    int col = ks * 8 + ((lane >> 3) & 1) * 4;
                    ldsm4(q0, q1, q2, q3, smb + (VS_OFF + row * 68 + col) * 4);
#pragma unroll
                    for (int mi = 0; mi < 2; mi++) {
                        mma_tf32(acc[mi][2 * nip][0], acc[mi][2 * nip][1],
                                 acc[mi][2 * nip][2], acc[mi][2 * nip][3],
                                 afr[mi][0], afr[mi][1], afr[mi][2], afr[mi][3], q0, q1);
                        mma_tf32(acc[mi][2 * nip + 1][0], acc[mi][2 * nip + 1][1],
                                 acc[mi][2 * nip + 1][2], acc[mi][2 * nip + 1][3],
                                 afr[mi][0], afr[mi][1], afr[mi][2], afr[mi][3], q2, q3);
                    }
                }
            }
        }
        __syncthreads();

        // stage V(t+1) (Vst free now)
        if (t + 1 < NN / 64) {
            const float* Vn = Vp + (size_t)(t + 1) * 64;
#pragma unroll
            for (int r = 0; r < 12; r++) {
                int idx = tid + r * 512;
                int v = idx / 16, q = idx % 16;
                cpa16(smb + (VS_OFF + v * 68 + q * 4) * 4, Vn + (size_t)v * NN + q * 4);
            }
        }
        CP_COMMIT();
    }

    // ---- epilogue: divide by l, store Rt[b][i0+row][h*384 + col] ----
    float* Rp = Rt + ((size_t)b * NN + i0) * DVH + h * DX;
#pragma unroll
    for (int mi = 0; mi < 2; mi++) {
        int r0 = wm + mi * 16 + (lane >> 2);
        float ia = 1.f / sm[LS_OFF + r0];
        float ib = 1.f / sm[LS_OFF + r0 + 8];
#pragma unroll
        for (int ni = 0; ni < 12; ni++) {
            int c0 = wn + ni * 8 + (lane & 3) * 2;
            *(float2*)(Rp + (size_t)r0 * DVH + c0) =
                make_float2(acc[mi][ni][0] * ia, acc[mi][ni][1] * ia);
            *(float2*)(Rp + (size_t)(r0 + 8) * DVH + c0) =
                make_float2(acc[mi][ni][2] * ib, acc[mi][ni][3] * ib);
        }
    }
}

// ---------------------------------------------------------------------------
extern "C" void kernel_launch(void* const* d_in, const int* in_sizes, int n_in,
                              void* d_out, int out_size)
{
    const float* X   = (const float*)d_in[0];
    const float* W_q = (const float*)d_in[1];
    const float* W_k = (const float*)d_in[2];
    const float* W_v = (const float*)d_in[3];
    const float* W_r = (const float*)d_in[4];
    float* out = (float*)d_out;

    float *gQt, *gKt, *gV, *gRt;
    cudaGetSymbolAddress((void**)&gQt, g_Qt);
    cudaGetSymbolAddress((void**)&gKt, g_Kt);
    cudaGetSymbolAddress((void**)&gV,  g_V);
    cudaGetSymbolAddress((void**)&gRt, g_Rt);

    static int smem_set = 0;
    if (!smem_set) {
        cudaFuncSetAttribute(attn_fused, cudaFuncAttributeMaxDynamicSharedMemorySize,
                             SM_FLOATS * 4);
        smem_set = 1;
    }

    const dim3 blk(256);

    // Q projection -> g_Qt[b][tok][qglob], tf32-rounded
    gemm_tf32<<<dim3(NN / 64, DX / 128, BB), blk>>>(
        W_q, X, gQt, DX, DX, DX,
        0, 0, (long)NN * DX, 0, (long)NN * DX, 0,
        1, DX, 1, 1);
    // K projection -> g_Kt
    gemm_tf32<<<dim3(NN / 64, DX / 128, BB), blk>>>(
        W_k, X, gKt, DX, DX, DX,
        0, 0, (long)NN * DX, 0, (long)NN * DX, 0,
        1, DX, 1, 1);
    // V projection -> g_V[b][vglob][tok] (m-major), tf32-rounded
    gemm_tf32<<<dim3(NN / 64, DVH / 128, BB), blk>>>(
        W_v, X, gV, DX, DX, DX,
        0, 0, (long)NN * DX, 0, (long)DVH * NN, 0,
        NN, 1, 1, 1);

    // fused attention -> g_Rt[b][tok][vglob]
    attn_fused<<<dim3(NN / 128, HH, BB), dim3(512), SM_FLOATS * 4>>>(gQt, gKt, gV, gRt);

    // output projection -> out[b][tok][d]
    gemm_tf32<<<dim3(NN / 64, DX / 128, BB), blk>>>(
        W_r, gRt, out, DVH, DVH, DVH,
        0, 0, (long)NN * DVH, 0, (long)NN * DX, 0,
        1, DX, 1, 0);
}